// round 11
// baseline (speedup 1.0000x reference)
#include <cuda_runtime.h>
#include <math.h>
#include <stdint.h>

// Problem constants (B=8, L=4096, D=1024, fp32)
#define BB 8
#define LL 4096
#define ND (LL - 1)        // 4095 deltas per batch
#define NI (LL - 2)        // 4094 loss terms per batch
#define TC 111             // terms per block
#define NDEL (TC + 1)      // 112 deltas per block
#define NROWS (NDEL + 1)   // 113 rows per block
#define XBLK 37            // 37*111 = 4107 >= 4094
// grid = (37, 8) = 296 = 148 SMs * 2 CTAs -> ONE perfectly balanced wave

#define CHUNK_ROWS 4
#define CHUNK_BYTES (CHUNK_ROWS * 4096)   // 16 KB
#define DEPTH 4                            // ring slots (64 KB dynamic smem)

// Accumulators. Zero-initialized at load; last block resets them each launch.
__device__ float g_ws;
__device__ float g_ms;
__device__ unsigned int g_ticket;

__device__ __forceinline__ float sqnorm_diff(float4 a, float4 b) {
    float dx = a.x - b.x, dy = a.y - b.y, dz = a.z - b.z, dw = a.w - b.w;
    return fmaf(dx, dx, fmaf(dy, dy, fmaf(dz, dz, dw * dw)));
}

__device__ __forceinline__ uint32_t smem_u32(const void* p) {
    return (uint32_t)__cvta_generic_to_shared(p);
}
__device__ __forceinline__ void mbar_init(uint32_t mbar, uint32_t cnt) {
    asm volatile("mbarrier.init.shared.b64 [%0], %1;" :: "r"(mbar), "r"(cnt) : "memory");
}
__device__ __forceinline__ void mbar_expect_tx(uint32_t mbar, uint32_t bytes) {
    asm volatile("mbarrier.arrive.expect_tx.shared.b64 _, [%0], %1;"
                 :: "r"(mbar), "r"(bytes) : "memory");
}
__device__ __forceinline__ void mbar_arrive(uint32_t mbar) {
    asm volatile("mbarrier.arrive.shared.b64 _, [%0];" :: "r"(mbar) : "memory");
}
__device__ __forceinline__ void mbar_wait(uint32_t mbar, uint32_t phase) {
    asm volatile(
        "{\n\t"
        ".reg .pred P;\n\t"
        "WAIT_%=:\n\t"
        "mbarrier.try_wait.parity.acquire.cta.shared::cta.b64 P, [%0], %1, 0x989680;\n\t"
        "@P bra DONE_%=;\n\t"
        "bra WAIT_%=;\n\t"
        "DONE_%=:\n\t"
        "}"
        :: "r"(mbar), "r"(phase) : "memory");
}
__device__ __forceinline__ void bulk_ldg(uint32_t smem_dst, const void* gsrc,
                                         uint32_t bytes, uint32_t mbar) {
    asm volatile(
        "cp.async.bulk.shared::cta.global.mbarrier::complete_tx::bytes [%0], [%1], %2, [%3];"
        :: "r"(smem_dst), "l"(gsrc), "r"(bytes), "r"(mbar) : "memory");
}

// Fused kernel. Block (bx, b) owns terms t in [111*bx, 111*bx+111) ∩ [0, NI).
// Phase 1: bulk-TMA pipeline — elected thread streams 16 KB chunks (4 rows)
//          into a 4-slot smem ring via cp.async.bulk + mbarrier expect_tx
//          (no per-warp load-queue coupling); 8 warps consume rows (LDS.128,
//          4x sqnorm, 2 SHFL pre-reduce) and arrive on per-slot empty
//          barriers (count 8). Producer runs DEPTH=4 chunks ahead.
// Phase 2: warp w reduces deltas i ≡ w (mod 8): 2 LDS + 5 SHFL + sqrt.
// Phase 3: warp 0 computes 111 weighted terms (4/lane), one atomicAdd pair
//          per block; ticketed last block publishes out and resets state.
//
// Chunking: normal blocks need 113 rows -> 29 chunks (reads 3 spare rows,
// max global row 4000 < 4096: in-bounds). Last x-block (t0=3996) needs 100
// rows -> exactly 25 chunks ending at row 4095 (no OOB). Deltas beyond
// rows_needed-1 are never stored/used.
//
// rtp dtype hedge: buffer may be int64 or int32. Read as 16 int32 words;
// little-endian int64 values < 4096 => all odd words zero => take even words.
__global__ __launch_bounds__(256, 2) void fused_kernel(const float* __restrict__ states,
                                                       const float* __restrict__ reasoning_mask,
                                                       const int* __restrict__ rtp_raw,
                                                       float* __restrict__ out) {
    extern __shared__ float4 ring[];                  // DEPTH * 1024 float4 = 64 KB
    __shared__ float s_part[NDEL * 64];               // 8 group-sums x 8 warps
    __shared__ float delta_sm[NDEL];
    __shared__ unsigned long long mb_full[DEPTH];
    __shared__ unsigned long long mb_empty[DEPTH];

    const int b   = blockIdx.y;
    const int t0  = blockIdx.x * TC;
    const int tid = threadIdx.x;
    const int warp = tid >> 5;
    const int lane = tid & 31;
    const unsigned int nblocks = gridDim.x * gridDim.y;

    const char* __restrict__ gbase =
        reinterpret_cast<const char*>(states) + (size_t)b * LL * 4096;

    const int rows_needed = (LL - t0 < NROWS) ? (LL - t0) : NROWS;  // 113 or 100
    const int ndel_local  = rows_needed - 1;                         // 112 or 99
    const int nchunks     = (rows_needed + CHUNK_ROWS - 1) / CHUNK_ROWS;  // 29 or 25

    uint32_t ring_s = smem_u32(ring);

    // ---- init barriers + prologue issue ----
    if (tid == 0) {
        #pragma unroll
        for (int s = 0; s < DEPTH; s++) {
            mbar_init(smem_u32(&mb_full[s]), 1);
            mbar_init(smem_u32(&mb_empty[s]), 8);
        }
    }
    __syncthreads();
    if (tid == 0) {
        #pragma unroll
        for (int s = 0; s < DEPTH; s++) {
            if (s < nchunks) {
                mbar_expect_tx(smem_u32(&mb_full[s]), CHUNK_BYTES);
                bulk_ldg(ring_s + (uint32_t)(s * CHUNK_BYTES),
                         gbase + (size_t)(t0 + s * CHUNK_ROWS) * 4096,
                         CHUNK_BYTES, smem_u32(&mb_full[s]));
            }
        }
    }

    const int sp_col = warp * 8 + lane;   // valid when lane < 8
    const uint32_t toff = (uint32_t)(tid * 16);
    float4 prev = make_float4(0.f, 0.f, 0.f, 0.f);

    // ---- main pipeline loop ----
    for (int ch = 0; ch < nchunks; ch++) {
        const int slot = ch & (DEPTH - 1);
        const uint32_t phase = (uint32_t)(ch / DEPTH) & 1u;

        mbar_wait(smem_u32(&mb_full[slot]), phase);

        const char* sp = reinterpret_cast<const char*>(ring) + slot * CHUNK_BYTES + toff;
        float4 c0 = *reinterpret_cast<const float4*>(sp);
        float4 c1 = *reinterpret_cast<const float4*>(sp + 4096);
        float4 c2 = *reinterpret_cast<const float4*>(sp + 8192);
        float4 c3 = *reinterpret_cast<const float4*>(sp + 12288);

        if (ch == 0) prev = c0;

        float s0 = sqnorm_diff(c0, prev);
        float s1 = sqnorm_diff(c1, c0);
        float s2 = sqnorm_diff(c2, c1);
        float s3 = sqnorm_diff(c3, c2);
        s0 += __shfl_xor_sync(0xffffffffu, s0, 16);
        s1 += __shfl_xor_sync(0xffffffffu, s1, 16);
        s2 += __shfl_xor_sync(0xffffffffu, s2, 16);
        s3 += __shfl_xor_sync(0xffffffffu, s3, 16);
        s0 += __shfl_xor_sync(0xffffffffu, s0, 8);
        s1 += __shfl_xor_sync(0xffffffffu, s1, 8);
        s2 += __shfl_xor_sync(0xffffffffu, s2, 8);
        s3 += __shfl_xor_sync(0xffffffffu, s3, 8);

        const int ib = 4 * ch - 1;   // delta index of s0
        if (lane < 8) {
            if (ib >= 0 && ib < ndel_local)  s_part[ib * 64 + sp_col]       = s0;
            if (ib + 1 < ndel_local)         s_part[(ib + 1) * 64 + sp_col] = s1;
            if (ib + 2 < ndel_local)         s_part[(ib + 2) * 64 + sp_col] = s2;
            if (ib + 3 < ndel_local)         s_part[(ib + 3) * 64 + sp_col] = s3;
        }
        prev = c3;

        if (lane == 0) mbar_arrive(smem_u32(&mb_empty[slot]));

        // producer: refill this slot with chunk ch+DEPTH once all warps drained it
        if (tid == 0) {
            const int nx = ch + DEPTH;
            if (nx < nchunks) {
                mbar_wait(smem_u32(&mb_empty[slot]), phase);
                mbar_expect_tx(smem_u32(&mb_full[slot]), CHUNK_BYTES);
                bulk_ldg(ring_s + (uint32_t)(slot * CHUNK_BYTES),
                         gbase + (size_t)(t0 + nx * CHUNK_ROWS) * 4096,
                         CHUNK_BYTES, smem_u32(&mb_full[slot]));
            }
        }
    }

    __syncthreads();

    // ---- Phase 2: reduce 64 partials per delta (warp w: i ≡ w mod 8) ----
    for (int i = warp; i < ndel_local; i += 8) {
        float v = s_part[i * 64 + lane] + s_part[i * 64 + lane + 32];
        #pragma unroll
        for (int o = 16; o > 0; o >>= 1)
            v += __shfl_xor_sync(0xffffffffu, v, o);
        if (lane == 0) delta_sm[i] = sqrtf(v);
    }

    __syncthreads();

    // ---- Phase 3: loss terms, warp 0 only (111 terms, 4 per lane) ----
    if (warp == 0) {
        int odd_or = 0;
        #pragma unroll
        for (int i = 1; i < 16; i += 2) odd_or |= rtp_raw[i];
        const int rtp_b = (odd_or == 0) ? rtp_raw[2 * b] : rtp_raw[b];

        float ws = 0.0f, ms = 0.0f;
        #pragma unroll
        for (int h = 0; h < 4; h++) {
            const int li = lane + 32 * h;     // local term index
            const int t = t0 + li;
            if (li < TC && t < NI) {
                float di = fmaxf(delta_sm[li + 1] - delta_sm[li], 0.0f);
                const float m = reasoning_mask[b * LL + t + 2];
                int dist = rtp_b - t - 2;
                if (dist < 0) dist = 0;
                const float w = (dist < 5) ? (2.0f + (float)(5 - dist) * 0.5f) : 1.0f;
                ws += di * m * w;
                ms += m;
            }
        }
        #pragma unroll
        for (int o = 16; o > 0; o >>= 1) {
            ws += __shfl_xor_sync(0xffffffffu, ws, o);
            ms += __shfl_xor_sync(0xffffffffu, ms, o);
        }
        if (lane == 0) {
            atomicAdd(&g_ws, ws);
            atomicAdd(&g_ms, ms);
            __threadfence();
            const unsigned int my = atomicAdd(&g_ticket, 1u);
            if (my == nblocks - 1u) {
                __threadfence();
                const float tws = *(volatile float*)&g_ws;
                const float tms = *(volatile float*)&g_ms;
                out[0] = tws / (tms + 1e-9f);
                // reset for next graph replay (all blocks done: safe)
                g_ws = 0.0f;
                g_ms = 0.0f;
                g_ticket = 0u;
            }
        }
    }
}

extern "C" void kernel_launch(void* const* d_in, const int* in_sizes, int n_in,
                              void* d_out, int out_size) {
    const float* states = (const float*)d_in[0];
    const float* rmask  = (const float*)d_in[1];
    const int*   rtp    = (const int*)d_in[2];
    float*       out    = (float*)d_out;

    cudaFuncSetAttribute(fused_kernel,
                         cudaFuncAttributeMaxDynamicSharedMemorySize,
                         DEPTH * CHUNK_BYTES);

    dim3 grid(XBLK, BB);   // (37, 8) = 296 blocks = 148 SMs x 2
    fused_kernel<<<grid, 256, DEPTH * CHUNK_BYTES>>>(states, rmask, rtp, out);
}

// round 12
// speedup vs baseline: 1.7272x; 1.7272x over previous
#include <cuda_runtime.h>
#include <math.h>

// Problem constants (B=8, L=4096, D=1024, fp32)
#define BB 8
#define LL 4096
#define ND (LL - 1)       // 4095 deltas per batch
#define NI (LL - 2)       // 4094 loss terms per batch
#define TC 56             // terms per block
#define NDEL (TC + 1)     // 57 deltas per block (rows t0 .. t0+57)
#define XBLK 74           // blocks per batch: 74*56 = 4144 >= 4094
// grid = (74, 8) = 592 = 148 SMs * 4 CTAs -> ONE perfectly balanced wave

// Accumulators. Zero-initialized at load; last block resets them each launch.
__device__ float g_ws;
__device__ float g_ms;
__device__ unsigned int g_ticket;

__device__ __forceinline__ float sqnorm_diff(float4 a, float4 b) {
    float dx = a.x - b.x, dy = a.y - b.y, dz = a.z - b.z, dw = a.w - b.w;
    return fmaf(dx, dx, fmaf(dy, dy, fmaf(dz, dz, dw * dw)));
}

// Fused kernel (R8 structure + __ldcs streaming loads).
// Block (bx, b) owns terms t in [56*bx, 56*bx+56) ∩ [0, NI).
// Phase 1: stream 58 rows in chunks of 8 (8 LDG.128.CS in flight per thread,
//          64-reg budget at 4 CTAs/SM), ONE xor-16 shfl per delta, lanes
//          0..15 store into s_part[i][warp*16+lane]  (57 x 128, ~29 KB).
// Phase 2: warp w reduces deltas i ≡ w (mod 8): 4 LDS + 5 SHFL + sqrt.
// Phase 3: warp 0 computes the 56 weighted loss terms (2 per lane), one
//          atomicAdd pair per block; ticketed last block publishes + resets.
//
// rtp dtype hedge: buffer may be int64 or int32. Read as 16 int32 words;
// little-endian int64 values < 4096 => all odd words zero => take even words.
__global__ __launch_bounds__(256, 4) void fused_kernel(const float* __restrict__ states,
                                                       const float* __restrict__ reasoning_mask,
                                                       const int* __restrict__ rtp_raw,
                                                       float* __restrict__ out) {
    const int b   = blockIdx.y;
    const int t0  = blockIdx.x * TC;
    const int tid = threadIdx.x;
    const int warp = tid >> 5;
    const int lane = tid & 31;
    const unsigned int nblocks = gridDim.x * gridDim.y;

    const float4* __restrict__ base =
        reinterpret_cast<const float4*>(states + (size_t)b * LL * (size_t)1024);

    __shared__ float s_part[NDEL][128];    // 16 half-warp sums per warp-slot
    __shared__ float delta_sm[NDEL];

    const int sp_col = warp * 16 + lane;   // valid when lane < 16

    // ---- Phase 1: stream rows t0 .. t0+57, emit 57 pre-reduced partials ----
    if (t0 + NDEL <= LL - 1) {
        // Clean path: 7 chunks x 8 rows + 1 tail row. Streaming (evict-first).
        float4 prev = __ldcs(base + (size_t)t0 * 256 + tid);
        #pragma unroll
        for (int ch = 0; ch < 7; ch++) {
            const size_t r = (size_t)(t0 + 8 * ch + 1) * 256 + tid;
            float4 c[8];
            #pragma unroll
            for (int j = 0; j < 8; j++) c[j] = __ldcs(base + r + 256 * j);

            float s[8];
            s[0] = sqnorm_diff(c[0], prev);
            #pragma unroll
            for (int j = 1; j < 8; j++) s[j] = sqnorm_diff(c[j], c[j - 1]);

            #pragma unroll
            for (int j = 0; j < 8; j++) {
                float v = s[j] + __shfl_xor_sync(0xffffffffu, s[j], 16);
                if (lane < 16) s_part[8 * ch + j][sp_col] = v;
            }
            prev = c[7];
        }
        float4 cl = __ldcs(base + (size_t)(t0 + NDEL) * 256 + tid);
        float vl = sqnorm_diff(cl, prev);
        vl += __shfl_xor_sync(0xffffffffu, vl, 16);
        if (lane < 16) s_part[NDEL - 1][sp_col] = vl;
    } else {
        // Guarded path (last x-block only): clamp rows; out-of-range deltas
        // become 0 (diff of identical clamped rows) and are unused anyway.
        float4 prev = __ldcs(base + (size_t)t0 * 256 + tid);
        #pragma unroll 4
        for (int i = 0; i < NDEL; i++) {
            int row = t0 + i + 1;
            if (row > LL - 1) row = LL - 1;
            float4 cur = __ldcs(base + (size_t)row * 256 + tid);
            float v = sqnorm_diff(cur, prev);
            v += __shfl_xor_sync(0xffffffffu, v, 16);
            if (lane < 16) s_part[i][sp_col] = v;
            prev = cur;
        }
    }

    __syncthreads();

    // ---- Phase 2: reduce 128 partials per delta. Warp w handles deltas
    //      i = w, w+8, ... < NDEL (conflict-free LDS). ----
    for (int i = warp; i < NDEL; i += 8) {
        float v = s_part[i][lane] + s_part[i][lane + 32]
                + s_part[i][lane + 64] + s_part[i][lane + 96];
        #pragma unroll
        for (int o = 16; o > 0; o >>= 1)
            v += __shfl_xor_sync(0xffffffffu, v, o);
        if (lane == 0) delta_sm[i] = sqrtf(v);
    }

    __syncthreads();

    // ---- Phase 3: loss terms, warp 0 only (56 terms, 2 per lane) ----
    if (warp == 0) {
        int odd_or = 0;
        #pragma unroll
        for (int i = 1; i < 16; i += 2) odd_or |= rtp_raw[i];
        const int rtp_b = (odd_or == 0) ? rtp_raw[2 * b] : rtp_raw[b];

        float ws = 0.0f, ms = 0.0f;
        #pragma unroll
        for (int h = 0; h < 2; h++) {
            const int li = lane + 32 * h;     // local term index
            const int t = t0 + li;
            if (li < TC && t < NI) {
                float di = fmaxf(delta_sm[li + 1] - delta_sm[li], 0.0f);
                const float m = reasoning_mask[b * LL + t + 2];
                int dist = rtp_b - t - 2;
                if (dist < 0) dist = 0;
                const float w = (dist < 5) ? (2.0f + (float)(5 - dist) * 0.5f) : 1.0f;
                ws += di * m * w;
                ms += m;
            }
        }
        #pragma unroll
        for (int o = 16; o > 0; o >>= 1) {
            ws += __shfl_xor_sync(0xffffffffu, ws, o);
            ms += __shfl_xor_sync(0xffffffffu, ms, o);
        }
        if (lane == 0) {
            atomicAdd(&g_ws, ws);
            atomicAdd(&g_ms, ms);
            __threadfence();
            const unsigned int my = atomicAdd(&g_ticket, 1u);
            if (my == nblocks - 1u) {
                __threadfence();
                const float tws = *(volatile float*)&g_ws;
                const float tms = *(volatile float*)&g_ms;
                out[0] = tws / (tms + 1e-9f);
                // reset for next graph replay (all blocks done: safe)
                g_ws = 0.0f;
                g_ms = 0.0f;
                g_ticket = 0u;
            }
        }
    }
}

extern "C" void kernel_launch(void* const* d_in, const int* in_sizes, int n_in,
                              void* d_out, int out_size) {
    const float* states = (const float*)d_in[0];
    const float* rmask  = (const float*)d_in[1];
    const int*   rtp    = (const int*)d_in[2];
    float*       out    = (float*)d_out;

    dim3 grid(XBLK, BB);   // (74, 8) = 592 blocks = 148 SMs x 4
    fused_kernel<<<grid, 256>>>(states, rmask, rtp, out);
}